// round 11
// baseline (speedup 1.0000x reference)
#include <cuda_runtime.h>
#include <cstdint>

// PSRoIPool via per-(plane,batch) ROW-prefix sums in smem (no column scan).
// x (4, 1029, 96, 96) fp32, rois (512,5) fp32, out (512, 21, 7, 7) fp32.
// Grid (1029, 4): block = plane p of batch b.
//   stage (float4 coalesced) -> serial row prefix (96 owner threads,
//   stride-97 conflict-free) -> per-roi window sum as sum over rows of
//   R[hy][we-1] - R[hy][ws-1].
//
// NUMERIC CONTRACT (verified R5): bin sizes are reciprocal-multiplies
// __fmul_rn(extent, fl(1/7)) — NOT divisions. Do not change.

#define C_TOT   1029
#define PH      7
#define PW      7
#define HH      96
#define WW      96
#define WP      97            // padded row stride (conflict-free)
#define PLANE   (HH*WW)
#define KROIS   512
#define NBATCH  4
#define SCALE   0.0625f
#define RCP7    0.1428571492433547973632812500f   // fl(1/7) = 0x3E124925
#define THREADS 256

__global__ __launch_bounds__(THREADS) void psroi_rowpfx(
    const float* __restrict__ x,
    const float* __restrict__ rois,
    float* __restrict__ out)
{
    __shared__ float sp[HH * WP];          // 37248 B
    const int p   = blockIdx.x;            // plane/channel 0..1028
    const int b   = blockIdx.y;            // batch 0..3
    const int ij  = p % (PH * PW);
    const int i   = ij / PW;
    const int j   = ij - i * PW;
    const int tid = threadIdx.x;

    // ---- Stage plane (b,p): coalesced float4 loads, padded scalar stores.
    const float4* __restrict__ src4 =
        (const float4*)(x + ((size_t)b * C_TOT + p) * PLANE);
    #pragma unroll
    for (int q = 0; q < PLANE / 4 / THREADS; ++q) {      // 9
        const int e    = tid + q * THREADS;              // float4 index
        const float4 v = __ldg(src4 + e);
        const int f    = e * 4;                          // flat float index
        const int row  = f / WW;
        const int base = row * WP + (f - row * WW);      // 96%4==0: same row
        sp[base + 0] = v.x;
        sp[base + 1] = v.y;
        sp[base + 2] = v.z;
        sp[base + 3] = v.w;
    }
    __syncthreads();

    // ---- Row prefix: thread t owns row t (stride-97 across lanes).
    if (tid < HH) {
        float run = 0.0f;
        const int base = tid * WP;
        #pragma unroll 8
        for (int c = 0; c < WW; ++c) { run += sp[base + c]; sp[base + c] = run; }
    }
    __syncthreads();

    // ---- Gather: rois k = tid, tid+256 with batch b.
    #pragma unroll
    for (int t = 0; t < 2; ++t) {
        const int k = tid + t * THREADS;
        const float* roi = rois + k * 5;
        if ((int)roi[0] != b) continue;

        const int sw = (int)floorf(__fmaf_rn(roi[1], SCALE, 0.5f));
        const int sh = (int)floorf(__fmaf_rn(roi[2], SCALE, 0.5f));
        const int ew = (int)floorf(__fmaf_rn(roi[3], SCALE, 0.5f));
        const int eh = (int)floorf(__fmaf_rn(roi[4], SCALE, 0.5f));
        const float bin_h = __fmul_rn((float)max(eh - sh, 1), RCP7);
        const float bin_w = __fmul_rn((float)max(ew - sw, 1), RCP7);
        const int hs = min(max((int)floorf(__fmul_rn((float)i,       bin_h)) + sh, 0), HH);
        const int he = min(max((int)ceilf (__fmul_rn((float)(i + 1), bin_h)) + sh, 0), HH);
        const int ws = min(max((int)floorf(__fmul_rn((float)j,       bin_w)) + sw, 0), WW);
        const int we = min(max((int)ceilf (__fmul_rn((float)(j + 1), bin_w)) + sw, 0), WW);

        const int area = (he - hs) * (we - ws);
        float val = 0.0f;
        if (area > 0) {
            float s = 0.0f;
            const float* __restrict__ right = sp + (we - 1);
            if (ws > 0) {
                const float* __restrict__ left = sp + (ws - 1);
                for (int hy = hs; hy < he; ++hy)
                    s += right[hy * WP] - left[hy * WP];
            } else {
                for (int hy = hs; hy < he; ++hy)
                    s += right[hy * WP];
            }
            val = __fdiv_rn(s, (float)area);
        }
        out[k * C_TOT + p] = val;
    }
}

extern "C" void kernel_launch(void* const* d_in, const int* in_sizes, int n_in,
                              void* d_out, int out_size)
{
    const float* x;
    const float* rois;
    if (n_in >= 2 && in_sizes[0] == KROIS * 5) {
        rois = (const float*)d_in[0];
        x    = (const float*)d_in[1];
    } else {
        x    = (const float*)d_in[0];
        rois = (const float*)d_in[1];
    }
    float* out = (float*)d_out;

    dim3 grid(C_TOT, NBATCH);
    psroi_rowpfx<<<grid, THREADS>>>(x, rois, out);
}

// round 12
// speedup vs baseline: 1.2030x; 1.2030x over previous
#include <cuda_runtime.h>
#include <cstdint>

// PSRoIPool via per-(plane,batch) ROW-prefix sums in smem, float4 pipeline.
// x (4, 1029, 96, 96) fp32, rois (512,5) fp32, out (512, 21, 7, 7) fp32.
// Grid (1029, 4): block = plane p of batch b.
//   stage: LDG.128 coalesced -> STS.128 into padded float4 layout [96][25]
//   row scan: owner thread does 24 independent LDS.128, short FADD carry
//             chain (run += sum4), 24 STS.128
//   gather: window sum = sum over rows of R[hy][we-1] - R[hy][ws-1]
//
// NUMERIC CONTRACT (verified R5): bin sizes are reciprocal-multiplies
// __fmul_rn(extent, fl(1/7)) — NOT divisions. Do not change.

#define C_TOT   1029
#define PH      7
#define PW      7
#define HH      96
#define WW      96
#define W4      24            // float4s per row
#define WP4     25            // padded float4 row stride (100 floats)
#define WPF     (WP4*4)       // row stride in floats = 100
#define PLANE   (HH*WW)
#define KROIS   512
#define NBATCH  4
#define SCALE   0.0625f
#define RCP7    0.1428571492433547973632812500f   // fl(1/7) = 0x3E124925
#define THREADS 256

__global__ __launch_bounds__(THREADS) void psroi_rowpfx4(
    const float* __restrict__ x,
    const float* __restrict__ rois,
    float* __restrict__ out)
{
    __shared__ float4 sp4[HH * WP4];       // 38400 B
    float* const sp = (float*)sp4;
    const int p   = blockIdx.x;            // plane/channel 0..1028
    const int b   = blockIdx.y;            // batch 0..3
    const int ij  = p % (PH * PW);
    const int i   = ij / PW;
    const int j   = ij - i * PW;
    const int tid = threadIdx.x;

    // ---- Stage plane (b,p): coalesced LDG.128 -> STS.128 (padded layout).
    const float4* __restrict__ src4 =
        (const float4*)(x + ((size_t)b * C_TOT + p) * PLANE);
    #pragma unroll
    for (int q = 0; q < PLANE / 4 / THREADS; ++q) {      // 9
        const int e   = tid + q * THREADS;               // float4 index
        const int row = e / W4;
        const int c4  = e - row * W4;
        sp4[row * WP4 + c4] = __ldg(src4 + e);
    }
    __syncthreads();

    // ---- Row prefix: thread t owns row t. 24 independent vector loads,
    //      carry chain is only 24 FADDs (run += sum4).
    if (tid < HH) {
        float4* __restrict__ rr = sp4 + tid * WP4;
        float run = 0.0f;
        #pragma unroll
        for (int q = 0; q < W4; ++q) {
            float4 v = rr[q];
            const float s01 = v.x + v.y;
            const float s4  = s01 + (v.z + v.w);         // off-chain tree
            float4 o;
            o.x = run + v.x;
            o.y = run + s01;
            o.z = o.y + v.z;
            o.w = run + s4;
            rr[q] = o;
            run   = o.w;                                  // 1 FADD on chain
        }
    }
    __syncthreads();

    // ---- Gather: rois k = tid, tid+256 with batch b.
    #pragma unroll
    for (int t = 0; t < 2; ++t) {
        const int k = tid + t * THREADS;
        const float* roi = rois + k * 5;
        if ((int)roi[0] != b) continue;

        const int sw = (int)floorf(__fmaf_rn(roi[1], SCALE, 0.5f));
        const int sh = (int)floorf(__fmaf_rn(roi[2], SCALE, 0.5f));
        const int ew = (int)floorf(__fmaf_rn(roi[3], SCALE, 0.5f));
        const int eh = (int)floorf(__fmaf_rn(roi[4], SCALE, 0.5f));
        const float bin_h = __fmul_rn((float)max(eh - sh, 1), RCP7);
        const float bin_w = __fmul_rn((float)max(ew - sw, 1), RCP7);
        const int hs = min(max((int)floorf(__fmul_rn((float)i,       bin_h)) + sh, 0), HH);
        const int he = min(max((int)ceilf (__fmul_rn((float)(i + 1), bin_h)) + sh, 0), HH);
        const int ws = min(max((int)floorf(__fmul_rn((float)j,       bin_w)) + sw, 0), WW);
        const int we = min(max((int)ceilf (__fmul_rn((float)(j + 1), bin_w)) + sw, 0), WW);

        const int area = (he - hs) * (we - ws);
        float val = 0.0f;
        if (area > 0) {
            float s = 0.0f;
            const float* __restrict__ right = sp + (we - 1);
            if (ws > 0) {
                const float* __restrict__ left = sp + (ws - 1);
                for (int hy = hs; hy < he; ++hy)
                    s += right[hy * WPF] - left[hy * WPF];
            } else {
                for (int hy = hs; hy < he; ++hy)
                    s += right[hy * WPF];
            }
            val = __fdiv_rn(s, (float)area);
        }
        out[k * C_TOT + p] = val;
    }
}

extern "C" void kernel_launch(void* const* d_in, const int* in_sizes, int n_in,
                              void* d_out, int out_size)
{
    const float* x;
    const float* rois;
    if (n_in >= 2 && in_sizes[0] == KROIS * 5) {
        rois = (const float*)d_in[0];
        x    = (const float*)d_in[1];
    } else {
        x    = (const float*)d_in[0];
        rois = (const float*)d_in[1];
    }
    float* out = (float*)d_out;

    dim3 grid(C_TOT, NBATCH);
    psroi_rowpfx4<<<grid, THREADS>>>(x, rois, out);
}

// round 13
// speedup vs baseline: 1.2347x; 1.0264x over previous
#include <cuda_runtime.h>
#include <cstdint>

// PSRoIPool, two-stage: prep (decode+compact rois) + per-(plane,batch) row-
// prefix main kernel with table-driven gather.
// x (4, 1029, 96, 96) fp32, rois (512,5) fp32, out (512, 21, 7, 7) fp32.
//
// NUMERIC CONTRACT (verified R5): bin sizes are reciprocal-multiplies
// __fmul_rn(extent, fl(1/7)) — NOT divisions. Do not change.

#define C_TOT   1029
#define PH      7
#define PW      7
#define HH      96
#define WW      96
#define W4      24            // float4s per row
#define WP4     25            // padded float4 row stride (100 floats)
#define WPF     (WP4*4)
#define PLANE   (HH*WW)
#define KROIS   512
#define NBATCH  4
#define SCALE   0.0625f
#define RCP7    0.1428571492433547973632812500f   // fl(1/7) = 0x3E124925
#define THREADS 256

// Per-batch compacted roi tables (slot s = b*512 + n, n < g_cnt[b]).
__device__ int     g_cnt[NBATCH];
__device__ int     g_kk [NBATCH * KROIS];
__device__ int16_t g_hs [PH][NBATCH * KROIS];
__device__ int16_t g_he [PH][NBATCH * KROIS];
__device__ int16_t g_ws [PW][NBATCH * KROIS];
__device__ int16_t g_we [PW][NBATCH * KROIS];

__global__ __launch_bounds__(KROIS) void psroi_prep(const float* __restrict__ rois)
{
    const int k = threadIdx.x;
    if (k < NBATCH) g_cnt[k] = 0;
    __syncthreads();

    const float* roi = rois + k * 5;
    const int b  = (int)roi[0];
    const int sw = (int)floorf(__fmaf_rn(roi[1], SCALE, 0.5f));
    const int sh = (int)floorf(__fmaf_rn(roi[2], SCALE, 0.5f));
    const int ew = (int)floorf(__fmaf_rn(roi[3], SCALE, 0.5f));
    const int eh = (int)floorf(__fmaf_rn(roi[4], SCALE, 0.5f));
    const float bin_h = __fmul_rn((float)max(eh - sh, 1), RCP7);
    const float bin_w = __fmul_rn((float)max(ew - sw, 1), RCP7);

    const int s = (b << 9) + atomicAdd(&g_cnt[b], 1);
    g_kk[s] = k;
    #pragma unroll
    for (int i = 0; i < PH; ++i) {
        g_hs[i][s] = (int16_t)min(max((int)floorf(__fmul_rn((float)i,       bin_h)) + sh, 0), HH);
        g_he[i][s] = (int16_t)min(max((int)ceilf (__fmul_rn((float)(i + 1), bin_h)) + sh, 0), HH);
    }
    #pragma unroll
    for (int j = 0; j < PW; ++j) {
        g_ws[j][s] = (int16_t)min(max((int)floorf(__fmul_rn((float)j,       bin_w)) + sw, 0), WW);
        g_we[j][s] = (int16_t)min(max((int)ceilf (__fmul_rn((float)(j + 1), bin_w)) + sw, 0), WW);
    }
}

__global__ __launch_bounds__(THREADS) void psroi_main(
    const float* __restrict__ x,
    float* __restrict__ out)
{
    __shared__ float4 sp4[HH * WP4];       // 38400 B
    float* const sp = (float*)sp4;
    const int p   = blockIdx.x;            // plane/channel 0..1028
    const int b   = blockIdx.y;            // batch 0..3
    const int ij  = p % (PH * PW);
    const int i   = ij / PW;
    const int j   = ij - i * PW;
    const int tid = threadIdx.x;

    // ---- Stage plane (b,p): coalesced LDG.128 -> STS.128 (padded layout).
    const float4* __restrict__ src4 =
        (const float4*)(x + ((size_t)b * C_TOT + p) * PLANE);
    #pragma unroll
    for (int q = 0; q < PLANE / 4 / THREADS; ++q) {      // 9
        const int e   = tid + q * THREADS;
        const int row = e / W4;
        const int c4  = e - row * W4;
        sp4[row * WP4 + c4] = __ldg(src4 + e);
    }
    __syncthreads();

    // ---- Row prefix (float4 pipeline, short carry chain).
    if (tid < HH) {
        float4* __restrict__ rr = sp4 + tid * WP4;
        float run = 0.0f;
        #pragma unroll
        for (int q = 0; q < W4; ++q) {
            float4 v = rr[q];
            const float s01 = v.x + v.y;
            const float s4  = s01 + (v.z + v.w);
            float4 o;
            o.x = run + v.x;
            o.y = run + s01;
            o.z = o.y + v.z;
            o.w = run + s4;
            rr[q] = o;
            run   = o.w;
        }
    }
    __syncthreads();

    // ---- Gather: table-driven, compacted (all lanes active, no decode).
    const int cnt = g_cnt[b];
    for (int n = tid; n < cnt; n += THREADS) {
        const int s  = (b << 9) + n;
        const int hs = g_hs[i][s];
        const int he = g_he[i][s];
        const int ws = g_ws[j][s];
        const int we = g_we[j][s];
        const int kk = g_kk[s];

        const int area = (he - hs) * (we - ws);
        float val = 0.0f;
        if (area > 0) {
            float acc = 0.0f;
            const float* __restrict__ right = sp + (we - 1);
            if (ws > 0) {
                const float* __restrict__ left = sp + (ws - 1);
                for (int hy = hs; hy < he; ++hy)
                    acc += right[hy * WPF] - left[hy * WPF];
            } else {
                for (int hy = hs; hy < he; ++hy)
                    acc += right[hy * WPF];
            }
            val = __fdiv_rn(acc, (float)area);
        }
        out[kk * C_TOT + p] = val;
    }
}

extern "C" void kernel_launch(void* const* d_in, const int* in_sizes, int n_in,
                              void* d_out, int out_size)
{
    const float* x;
    const float* rois;
    if (n_in >= 2 && in_sizes[0] == KROIS * 5) {
        rois = (const float*)d_in[0];
        x    = (const float*)d_in[1];
    } else {
        x    = (const float*)d_in[0];
        rois = (const float*)d_in[1];
    }
    float* out = (float*)d_out;

    psroi_prep<<<1, KROIS>>>(rois);
    dim3 grid(C_TOT, NBATCH);
    psroi_main<<<grid, THREADS>>>(x, out);
}